// round 15
// baseline (speedup 1.0000x reference)
#include <cuda_runtime.h>
#include <cuda_bf16.h>
#include <math.h>

// Problem constants (fixed by the reference: B,H,W = 16,512,512)
#define BB 16
#define HH 512
#define WW 512
#define NPIX (BB * HH * WW)          // 4,194,304
#define TPB 256
#define NBLK (NPIX / TPB)            // 16,384

// Per-batch precomputed constants: {a0, a1, a2, cp} {sr*sp, cr*sp, finv, 0}
__device__ float4 g_const[BB * 2];

__global__ void precompute_kernel(const float* __restrict__ roll,
                                  const float* __restrict__ pitch,
                                  const float* __restrict__ focal) {
    int b = threadIdx.x;
    if (b >= BB) return;
    float r = roll[b], p = pitch[b], f = focal[b];
    float sr = sinf(r), cr = cosf(r);
    float sp = sinf(p), cp = cosf(p);
    float a0 = -sr * cp;
    float a1 = -cr * cp;
    float a2 = -sp;
    float finv = 1.0f / f;
    g_const[b * 2 + 0] = make_float4(a0, a1, a2, cp);
    g_const[b * 2 + 1] = make_float4(sr * sp, cr * sp, finv, 0.0f);
}

__global__ __launch_bounds__(TPB)
void jacobian_kernel(float* __restrict__ out) {
    __shared__ float s[TPB * 9];     // 9216 bytes

    int tid = threadIdx.x;
    int p   = blockIdx.x * TPB + tid;        // global pixel index
    int b   = p >> 18;                        // / (512*512)
    int rem = p & ((1 << 18) - 1);
    int i   = rem >> 9;                       // row (y)
    int j   = rem & 511;                      // col (x)

    float4 ca = g_const[b * 2 + 0];
    float4 cb = g_const[b * 2 + 1];
    float a0 = ca.x, a1 = ca.y, a2 = ca.z, cp = ca.w;
    float srsp = cb.x, crsp = cb.y, finv = cb.z;

    // uv = (xy - c)/f ; xs = j+0.5, ys = i+0.5 ; c = (W/2, H/2)
    float u = ((float)j + 0.5f - 0.5f * (float)WW) * finv;
    float v = ((float)i + 0.5f - 0.5f * (float)HH) * finv;

    // proj = abc[:2] - c3*uv  (c3 = a2)
    float p0 = fmaf(-a2, u, a0);
    float p1 = fmaf(-a2, v, a1);
    float n2 = fmaf(p0, p0, p1 * p1);
    float sN = rsqrtf(fmaxf(n2, 1e-30f));    // 1/||proj||
    float q  = sN * sN;                       // 1/n2
    float M00 = sN * (1.0f - p0 * p0 * q);
    float M01 = -sN * p0 * p1 * q;
    float M11 = sN * (1.0f - p1 * p1 * q);

    // J_proj2delta = J_proj2abc @ J_rp  (2x2)
    float D00 = a1;                  // -cr*cp
    float D01 = fmaf(u, cp, srsp);   // sr*sp + u*cp
    float D10 = -a0;                 // sr*cp
    float D11 = fmaf(v, cp, crsp);   // cr*sp + v*cp
    // J_proj2f = a2*uv*finv
    float g0 = a2 * u * finv;
    float g1 = a2 * v * finv;

    float o00 = fmaf(M00, D00, M01 * D10);
    float o01 = fmaf(M00, D01, M01 * D11);
    float o02 = fmaf(M00, g0,  M01 * g1);
    float o10 = fmaf(M01, D00, M11 * D10);
    float o11 = fmaf(M01, D01, M11 * D11);
    float o12 = fmaf(M01, g0,  M11 * g1);

    // Lat row: uv1 = (u, v, 1)
    float r2  = fmaf(u, u, v * v);
    float n3  = r2 + 1.0f;
    float rn3 = rsqrtf(n3);
    float q3  = rn3 * rn3;                    // 1/n3
    float o20 = rn3 * fmaf(u, a1, -v * a0);
    float o21 = rn3 * (fmaf(u, srsp, v * crsp) - cp);
    float d   = fmaf(u, a0, v * a1);
    float o22 = rn3 * finv * fmaf(q3 * r2, d + a2, -d);

    // Stage into smem: linear layout = output layout of this block.
    // tid*9 + k mod 32 distinct across lanes (gcd(9,32)=1) -> conflict-free.
    int base = tid * 9;
    s[base + 0] = o00; s[base + 1] = o01; s[base + 2] = o02;
    s[base + 3] = o10; s[base + 4] = o11; s[base + 5] = o12;
    s[base + 6] = o20; s[base + 7] = o21; s[base + 8] = o22;
    __syncthreads();

    // Coalesced float4 writeback: 2304 floats = 576 float4 per block.
    const float4* s4 = (const float4*)s;
    float4* o4 = (float4*)out + (size_t)blockIdx.x * 576;
    o4[tid]       = s4[tid];
    o4[tid + 256] = s4[tid + 256];
    if (tid < 64) o4[tid + 512] = s4[tid + 512];
}

extern "C" void kernel_launch(void* const* d_in, const int* in_sizes, int n_in,
                              void* d_out, int out_size) {
    const float* roll  = (const float*)d_in[0];
    const float* pitch = (const float*)d_in[1];
    const float* focal = (const float*)d_in[2];
    float* out = (float*)d_out;

    precompute_kernel<<<1, 32>>>(roll, pitch, focal);
    jacobian_kernel<<<NBLK, TPB>>>(out);
}

// round 16
// speedup vs baseline: 1.0094x; 1.0094x over previous
#include <cuda_runtime.h>
#include <cuda_bf16.h>
#include <math.h>

// Problem constants (fixed by the reference: B,H,W = 16,512,512)
#define BB 16
#define HH 512
#define WW 512
#define NPIX (BB * HH * WW)          // 4,194,304
#define TPB 256
#define NBLK (NPIX / TPB)            // 16,384

// Per-batch precomputed constants: {a0, a1, a2, cp} {sr*sp, cr*sp, finv, 0}
__device__ float4 g_const[BB * 2];

__global__ void precompute_kernel(const float* __restrict__ roll,
                                  const float* __restrict__ pitch,
                                  const float* __restrict__ focal) {
    int b = threadIdx.x;
    if (b >= BB) return;
    float r = roll[b], p = pitch[b], f = focal[b];
    float sr = sinf(r), cr = cosf(r);
    float sp = sinf(p), cp = cosf(p);
    float a0 = -sr * cp;
    float a1 = -cr * cp;
    float a2 = -sp;
    float finv = 1.0f / f;
    g_const[b * 2 + 0] = make_float4(a0, a1, a2, cp);
    g_const[b * 2 + 1] = make_float4(sr * sp, cr * sp, finv, 0.0f);
}

__global__ __launch_bounds__(TPB)
void jacobian_kernel(float* __restrict__ out) {
    __shared__ float s[TPB * 9];     // 9216 bytes

    int tid = threadIdx.x;
    int p   = blockIdx.x * TPB + tid;        // global pixel index
    int b   = p >> 18;                        // / (512*512)
    int rem = p & ((1 << 18) - 1);
    int i   = rem >> 9;                       // row (y)
    int j   = rem & 511;                      // col (x)

    float4 ca = g_const[b * 2 + 0];
    float4 cb = g_const[b * 2 + 1];
    float a0 = ca.x, a1 = ca.y, a2 = ca.z, cp = ca.w;
    float srsp = cb.x, crsp = cb.y, finv = cb.z;

    // uv = (xy - c)/f ; xs = j+0.5, ys = i+0.5 ; c = (W/2, H/2)
    float u = ((float)j + 0.5f - 0.5f * (float)WW) * finv;
    float v = ((float)i + 0.5f - 0.5f * (float)HH) * finv;

    // proj = abc[:2] - c3*uv  (c3 = a2)
    float p0 = fmaf(-a2, u, a0);
    float p1 = fmaf(-a2, v, a1);
    float n2 = fmaf(p0, p0, p1 * p1);
    float sN = rsqrtf(fmaxf(n2, 1e-30f));    // 1/||proj||
    float q  = sN * sN;                       // 1/n2
    float M00 = sN * (1.0f - p0 * p0 * q);
    float M01 = -sN * p0 * p1 * q;
    float M11 = sN * (1.0f - p1 * p1 * q);

    // J_proj2delta = J_proj2abc @ J_rp  (2x2)
    float D00 = a1;                  // -cr*cp
    float D01 = fmaf(u, cp, srsp);   // sr*sp + u*cp
    float D10 = -a0;                 // sr*cp
    float D11 = fmaf(v, cp, crsp);   // cr*sp + v*cp
    // J_proj2f = a2*uv*finv
    float g0 = a2 * u * finv;
    float g1 = a2 * v * finv;

    float o00 = fmaf(M00, D00, M01 * D10);
    float o01 = fmaf(M00, D01, M01 * D11);
    float o02 = fmaf(M00, g0,  M01 * g1);
    float o10 = fmaf(M01, D00, M11 * D10);
    float o11 = fmaf(M01, D01, M11 * D11);
    float o12 = fmaf(M01, g0,  M11 * g1);

    // Lat row: uv1 = (u, v, 1)
    float r2  = fmaf(u, u, v * v);
    float n3  = r2 + 1.0f;
    float rn3 = rsqrtf(n3);
    float q3  = rn3 * rn3;                    // 1/n3
    float o20 = rn3 * fmaf(u, a1, -v * a0);
    float o21 = rn3 * (fmaf(u, srsp, v * crsp) - cp);
    float d   = fmaf(u, a0, v * a1);
    float o22 = rn3 * finv * fmaf(q3 * r2, d + a2, -d);

    // Stage into smem: linear layout = output layout of this block.
    // tid*9 + k mod 32 distinct across lanes (gcd(9,32)=1) -> conflict-free.
    int base = tid * 9;
    s[base + 0] = o00; s[base + 1] = o01; s[base + 2] = o02;
    s[base + 3] = o10; s[base + 4] = o11; s[base + 5] = o12;
    s[base + 6] = o20; s[base + 7] = o21; s[base + 8] = o22;
    __syncthreads();

    // Coalesced float4 writeback: 2304 floats = 576 float4 per block.
    const float4* s4 = (const float4*)s;
    float4* o4 = (float4*)out + (size_t)blockIdx.x * 576;
    o4[tid]       = s4[tid];
    o4[tid + 256] = s4[tid + 256];
    if (tid < 64) o4[tid + 512] = s4[tid + 512];
}

extern "C" void kernel_launch(void* const* d_in, const int* in_sizes, int n_in,
                              void* d_out, int out_size) {
    const float* roll  = (const float*)d_in[0];
    const float* pitch = (const float*)d_in[1];
    const float* focal = (const float*)d_in[2];
    float* out = (float*)d_out;

    precompute_kernel<<<1, 32>>>(roll, pitch, focal);
    jacobian_kernel<<<NBLK, TPB>>>(out);
}